// round 10
// baseline (speedup 1.0000x reference)
#include <cuda_runtime.h>
#include <math.h>

#define B_SZ   64
#define IN_SZ  1024
#define OUT_SZ 512
#define T_SZ   512
#define TAU_F  16.0f
#define V_TH   1.0f
#define WIN    8
#define NWE    32          // entry windows (spikes < 256 -> k <= 256)
#define NW     64          // total windows
#define ESTRIDE 1056
#define CHW    4           // prefetch depth in delta kernel
#define SENT_MAX 256
#define DFACT  0.60653065971263342f   // exp(-WIN/TAU) = exp(-0.5)

// Scratch (no dynamic allocation allowed)
__device__ float4 g_entries[B_SZ * ESTRIDE];        // {k, idx, u, p} sorted per batch
__device__ float  g_wT[IN_SZ * OUT_SZ];             // transposed weights [IN][OUT]
__device__ int    g_wstart[B_SZ * (NWE + 1)];       // per-batch window entry offsets
__device__ float2 g_P[B_SZ * NWE * OUT_SZ];         // per-window partials {PA, PB}
__device__ float  g_C[B_SZ * NWE * WIN * OUT_SZ];   // c1(dt) checkpoints (33.5 MB)

// ---------------------------------------------------------------------------
// Prep: blocks [0,64) bucket-sort spikes per batch (warp-shuffle scan) +
// window offsets; blocks [64,192) float4 tiled transpose.
// ---------------------------------------------------------------------------
__global__ void __launch_bounds__(1024) prep_kernel(const float* __restrict__ in_spike,
                                                    const float* __restrict__ w) {
    __shared__ int   hist[512];
    __shared__ int   scanv[512];
    __shared__ int   offs[512];
    __shared__ int   wsum[16];
    __shared__ float tile[64][65];

    const int bid = blockIdx.x;
    const int i   = threadIdx.x;

    if (bid < B_SZ) {
        const int b = bid;
        if (i < 512) hist[i] = 0;
        __syncthreads();

        const float s = in_spike[b * IN_SZ + i];
        int k = (int)floorf(s) + 1;
        k = max(1, min(k, NWE * WIN));           // k in [1, 256]
        atomicAdd(&hist[k], 1);
        __syncthreads();

        int h0 = 0, incl = 0;
        if (i < 512) {
            h0 = hist[i]; incl = h0;
            #pragma unroll
            for (int d = 1; d < 32; d <<= 1) {
                int n = __shfl_up_sync(0xffffffffu, incl, d);
                if ((i & 31) >= d) incl += n;
            }
            if ((i & 31) == 31) wsum[i >> 5] = incl;
        }
        __syncthreads();
        if (i < 16) {
            int s2 = wsum[i];
            #pragma unroll
            for (int d = 1; d < 16; d <<= 1) {
                int n = __shfl_up_sync(0x0000ffffu, s2, d);
                if (i >= d) s2 += n;
            }
            wsum[i] = s2;
        }
        __syncthreads();
        if (i < 512) {
            const int wrp = i >> 5;
            if (wrp > 0) incl += wsum[wrp - 1];
            scanv[i] = incl;          // inclusive
            offs[i]  = incl - h0;     // exclusive
        }
        __syncthreads();
        if (i <= NWE) g_wstart[b * (NWE + 1) + i] = (i == 0) ? 0 : scanv[i * WIN];

        const int pos = atomicAdd(&offs[k], 1);
        const int t0k = (k - 1) & ~(WIN - 1);
        const float rel = s - (float)t0k;              // [0, WIN)
        const float u = expf(rel * (1.0f / TAU_F));
        const float p = rel * u;
        g_entries[b * ESTRIDE + pos] = make_float4((float)k, (float)i, u, p);
    } else {
        // transpose 64x64 tile: w[OUT][IN] -> g_wT[IN][OUT]
        const int tb = bid - B_SZ;                 // 0..127
        const int i0 = (tb & 15) * 64;             // IN tile
        const int o0 = (tb >> 4) * 64;             // OUT tile
        const int tx = i & 15, ty = i >> 4;        // 16 x 64
        const float4 v = *(const float4*)&w[(o0 + ty) * IN_SZ + i0 + 4 * tx];
        tile[4 * tx + 0][ty] = v.x;
        tile[4 * tx + 1][ty] = v.y;
        tile[4 * tx + 2][ty] = v.z;
        tile[4 * tx + 3][ty] = v.w;
        __syncthreads();
        float4 r;
        r.x = tile[ty][4 * tx + 0];
        r.y = tile[ty][4 * tx + 1];
        r.z = tile[ty][4 * tx + 2];
        r.w = tile[ty][4 * tx + 3];
        *(float4*)&g_wT[(i0 + ty) * OUT_SZ + o0 + 4 * tx] = r;
    }
}

// ---------------------------------------------------------------------------
// Delta kernel (single entry pass): per (b, W, o) compute window-local
// checkpoint values c1(dt) = dt*dA(dt) - dB(dt) for dt = 1..WIN, and window
// partials (PA, PB) = (dA(WIN), dB(WIN)). 4 outputs/thread, grid (NWE, B).
// No start state, no threshold tests here — purely linear accumulation.
// ---------------------------------------------------------------------------
__global__ void __launch_bounds__(128) delta_kernel() {
    __shared__ float4 sent[SENT_MAX];
    const int W = blockIdx.x, b = blockIdx.y;
    const int tid = threadIdx.x;
    const int o = 4 * tid;

    const int start = g_wstart[b * (NWE + 1) + W];
    const int count = g_wstart[b * (NWE + 1) + W + 1] - start;
    const float kbase = (float)(W * WIN);

    float A0 = 0.f, B0 = 0.f, A1 = 0.f, B1 = 0.f;
    float A2 = 0.f, B2 = 0.f, A3 = 0.f, B3 = 0.f;

    const float4* __restrict__ ge = g_entries + b * ESTRIDE + start;
    const float4* __restrict__ wp = (const float4*)g_wT + tid;
    float* __restrict__ cp = g_C + (size_t)(b * NWE + W) * WIN * OUT_SZ + o;

    int t_dt = 1;
    for (int base = 0; base < count; base += SENT_MAX) {
        const int tcount = min(count - base, SENT_MAX);
        const int padded = (tcount + CHW - 1) & ~(CHW - 1);
        for (int j = tid; j < padded; j += 128) {
            float4 e = (j < tcount) ? ge[base + j] : make_float4(1e9f, 0.f, 0.f, 0.f);
            e.x -= kbase;                       // window-relative arrival (1..WIN)
            sent[j] = e;
        }
        __syncthreads();

        float4 wc[CHW];
        #pragma unroll
        for (int q = 0; q < CHW; q++) wc[q] = wp[((int)sent[q].y) << 7];
        const int nch = padded / CHW;
        for (int c = 0; c < nch; c++) {
            float4 wn[CHW];
            if (c + 1 < nch) {
                #pragma unroll
                for (int q = 0; q < CHW; q++)
                    wn[q] = wp[((int)sent[(c + 1) * CHW + q].y) << 7];
            }
            #pragma unroll
            for (int q = 0; q < CHW; q++) {
                const float4 e = sent[c * CHW + q];
                while ((float)t_dt < e.x && t_dt <= WIN) {   // uniform across block
                    const float tf = (float)t_dt;
                    float4 cv;
                    cv.x = fmaf(tf, A0, -B0);
                    cv.y = fmaf(tf, A1, -B1);
                    cv.z = fmaf(tf, A2, -B2);
                    cv.w = fmaf(tf, A3, -B3);
                    *(float4*)(cp + (t_dt - 1) * OUT_SZ) = cv;
                    t_dt++;
                }
                A0 = fmaf(wc[q].x, e.z, A0); B0 = fmaf(wc[q].x, e.w, B0);
                A1 = fmaf(wc[q].y, e.z, A1); B1 = fmaf(wc[q].y, e.w, B1);
                A2 = fmaf(wc[q].z, e.z, A2); B2 = fmaf(wc[q].z, e.w, B2);
                A3 = fmaf(wc[q].w, e.z, A3); B3 = fmaf(wc[q].w, e.w, B3);
            }
            #pragma unroll
            for (int q = 0; q < CHW; q++) wc[q] = wn[q];
        }
        __syncthreads();
    }
    while (t_dt <= WIN) {                                    // tail checkpoints
        const float tf = (float)t_dt;
        float4 cv;
        cv.x = fmaf(tf, A0, -B0);
        cv.y = fmaf(tf, A1, -B1);
        cv.z = fmaf(tf, A2, -B2);
        cv.w = fmaf(tf, A3, -B3);
        *(float4*)(cp + (t_dt - 1) * OUT_SZ) = cv;
        t_dt++;
    }
    float2* Pp = &g_P[(b * NWE + W) * OUT_SZ + o];
    *(float4*)(Pp)     = make_float4(A0, B0, A1, B1);
    *(float4*)(Pp + 2) = make_float4(A2, B2, A3, B3);
}

// ---------------------------------------------------------------------------
// Final kernel: one thread per (b,o). Serial window recurrence
//   As' = D (As + PA);  Bs' = D (Bs + PB) - WIN * As'
// Crossing at (W,dt) iff dt*As - Bs + c1[dt] >= th[dt]. Entry-free tail
// windows use c1 = 0. First crossing written directly (no atomics).
// ---------------------------------------------------------------------------
__global__ void __launch_bounds__(128) final_kernel(float* __restrict__ out) {
    const int b = blockIdx.y;
    const int o = blockIdx.x * 128 + threadIdx.x;

    float th[WIN];
    #pragma unroll
    for (int dt = 1; dt <= WIN; dt++)
        th[dt - 1] = V_TH * TAU_F * expf((float)dt * (1.0f / TAU_F) - 1.0f);

    const float* __restrict__ Cb = g_C + (size_t)(b * NWE) * WIN * OUT_SZ + o;
    const float2* __restrict__ Pb = g_P + b * NWE * OUT_SZ + o;

    float As = 0.f, Bs = 0.f;
    int res = 100000;

    for (int W = 0; W < NWE; W++) {
        float c[WIN];
        #pragma unroll
        for (int dt = 1; dt <= WIN; dt++)
            c[dt - 1] = Cb[(W * WIN + dt - 1) * OUT_SZ];      // 8-wide MLP
        const float2 P = Pb[W * OUT_SZ];
        #pragma unroll
        for (int dt = 1; dt <= WIN; dt++) {
            if (res == 100000 &&
                fmaf((float)dt, As, -Bs) + c[dt - 1] >= th[dt - 1])
                res = W * WIN + dt;
        }
        if (res != 100000) break;
        As = DFACT * (As + P.x);
        Bs = DFACT * (Bs + P.y) - (float)WIN * As;
    }
    if (res == 100000) {
        for (int W = NWE; W < NW; W++) {
            #pragma unroll
            for (int dt = 1; dt <= WIN; dt++) {
                if (res == 100000 && fmaf((float)dt, As, -Bs) >= th[dt - 1])
                    res = W * WIN + dt;
            }
            if (res != 100000) break;
            As = DFACT * As;
            Bs = DFACT * Bs - (float)WIN * As;
        }
    }
    out[b * OUT_SZ + o] = (res == 100000) ? (float)T_SZ : (float)min(res, T_SZ);
}

// ---------------------------------------------------------------------------
extern "C" void kernel_launch(void* const* d_in, const int* in_sizes, int n_in,
                              void* d_out, int out_size) {
    const float* in_spike = (const float*)d_in[0];  // [B, IN]
    const float* weight   = (const float*)d_in[1];  // [OUT, IN]
    float* out = (float*)d_out;                     // [B, OUT]
    (void)in_sizes; (void)n_in; (void)out_size;

    prep_kernel<<<B_SZ + 128, 1024>>>(in_spike, weight);
    delta_kernel<<<dim3(NWE, B_SZ), 128>>>();
    final_kernel<<<dim3(OUT_SZ / 128, B_SZ), 128>>>(out);
}

// round 11
// speedup vs baseline: 1.5875x; 1.5875x over previous
#include <cuda_runtime.h>
#include <math.h>

#define B_SZ   64
#define IN_SZ  1024
#define OUT_SZ 512
#define T_SZ   512
#define TAU_F  16.0f
#define V_TH   1.0f
#define WIN    8
#define NWE    32          // entry windows (spikes < 256 -> k <= 256)
#define NW     64          // total windows
#define ESTRIDE 1056
#define CHW    4           // prefetch depth in delta kernel
#define SENT_MAX 256
#define DFACT  0.60653065971263342f   // exp(-WIN/TAU) = exp(-0.5)

// Scratch (no dynamic allocation allowed)
__device__ float4 g_entries[B_SZ * ESTRIDE];        // {k, idx, u, p} sorted per batch
__device__ float  g_wT[IN_SZ * OUT_SZ];             // transposed weights [IN][OUT]
__device__ int    g_wstart[B_SZ * (NWE + 1)];       // per-batch window entry offsets
__device__ float2 g_P[B_SZ * NWE * OUT_SZ];         // per-window partials {PA, PB}
__device__ float2 g_S[B_SZ * NWE * OUT_SZ];         // per-window start state {A, B}
__device__ float  g_C[B_SZ * NWE * WIN * OUT_SZ];   // c1(dt) checkpoints (33.5 MB)

// ---------------------------------------------------------------------------
// Prep: blocks [0,64) bucket-sort spikes per batch (warp-shuffle scan) +
// window offsets + out init; blocks [64,192) float4 tiled transpose.
// ---------------------------------------------------------------------------
__global__ void __launch_bounds__(1024) prep_kernel(const float* __restrict__ in_spike,
                                                    const float* __restrict__ w,
                                                    float* __restrict__ out) {
    __shared__ int   hist[512];
    __shared__ int   scanv[512];
    __shared__ int   offs[512];
    __shared__ int   wsum[16];
    __shared__ float tile[64][65];

    const int bid = blockIdx.x;
    const int i   = threadIdx.x;

    if (bid < B_SZ) {
        const int b = bid;
        if (i < 512) { hist[i] = 0; out[b * OUT_SZ + i] = 512.0f; }  // init for atomicMin
        __syncthreads();

        const float s = in_spike[b * IN_SZ + i];
        int k = (int)floorf(s) + 1;
        k = max(1, min(k, NWE * WIN));           // k in [1, 256]
        atomicAdd(&hist[k], 1);
        __syncthreads();

        int h0 = 0, incl = 0;
        if (i < 512) {
            h0 = hist[i]; incl = h0;
            #pragma unroll
            for (int d = 1; d < 32; d <<= 1) {
                int n = __shfl_up_sync(0xffffffffu, incl, d);
                if ((i & 31) >= d) incl += n;
            }
            if ((i & 31) == 31) wsum[i >> 5] = incl;
        }
        __syncthreads();
        if (i < 16) {
            int s2 = wsum[i];
            #pragma unroll
            for (int d = 1; d < 16; d <<= 1) {
                int n = __shfl_up_sync(0x0000ffffu, s2, d);
                if (i >= d) s2 += n;
            }
            wsum[i] = s2;
        }
        __syncthreads();
        if (i < 512) {
            const int wrp = i >> 5;
            if (wrp > 0) incl += wsum[wrp - 1];
            scanv[i] = incl;          // inclusive
            offs[i]  = incl - h0;     // exclusive
        }
        __syncthreads();
        if (i <= NWE) g_wstart[b * (NWE + 1) + i] = (i == 0) ? 0 : scanv[i * WIN];

        const int pos = atomicAdd(&offs[k], 1);
        const int t0k = (k - 1) & ~(WIN - 1);
        const float rel = s - (float)t0k;              // [0, WIN)
        const float u = expf(rel * (1.0f / TAU_F));
        const float p = rel * u;
        g_entries[b * ESTRIDE + pos] = make_float4((float)k, (float)i, u, p);
    } else {
        // transpose 64x64 tile: w[OUT][IN] -> g_wT[IN][OUT]
        const int tb = bid - B_SZ;                 // 0..127
        const int i0 = (tb & 15) * 64;             // IN tile
        const int o0 = (tb >> 4) * 64;             // OUT tile
        const int tx = i & 15, ty = i >> 4;        // 16 x 64
        const float4 v = *(const float4*)&w[(o0 + ty) * IN_SZ + i0 + 4 * tx];
        tile[4 * tx + 0][ty] = v.x;
        tile[4 * tx + 1][ty] = v.y;
        tile[4 * tx + 2][ty] = v.z;
        tile[4 * tx + 3][ty] = v.w;
        __syncthreads();
        float4 r;
        r.x = tile[ty][4 * tx + 0];
        r.y = tile[ty][4 * tx + 1];
        r.z = tile[ty][4 * tx + 2];
        r.w = tile[ty][4 * tx + 3];
        *(float4*)&g_wT[(i0 + ty) * OUT_SZ + o0 + 4 * tx] = r;
    }
}

// ---------------------------------------------------------------------------
// Delta kernel (the single entry x weight gather pass). Per (b, W, o):
// checkpoints c1(dt) = dt*dA(dt) - dB(dt), dt = 1..WIN (staged in SMEM,
// dumped coalesced at end) and window partials (PA,PB) = (dA(WIN), dB(WIN)).
// 4 outputs/thread, grid (NWE, B). Structure mirrors R8's window_kernel.
// ---------------------------------------------------------------------------
__global__ void __launch_bounds__(128) delta_kernel() {
    __shared__ float4 sent[SENT_MAX];          // 4 KB
    __shared__ float4 schk[WIN][128];          // 16 KB checkpoint staging
    const int W = blockIdx.x, b = blockIdx.y;
    const int tid = threadIdx.x;
    const int o = 4 * tid;

    const int start = g_wstart[b * (NWE + 1) + W];
    const int count = g_wstart[b * (NWE + 1) + W + 1] - start;
    const float kbase = (float)(W * WIN);

    float A0 = 0.f, B0 = 0.f, A1 = 0.f, B1 = 0.f;
    float A2 = 0.f, B2 = 0.f, A3 = 0.f, B3 = 0.f;

    const float4* __restrict__ ge = g_entries + b * ESTRIDE + start;
    const float4* __restrict__ wp = (const float4*)g_wT + tid;

    int t_dt = 1;
    for (int base = 0; base < count; base += SENT_MAX) {
        const int tcount = min(count - base, SENT_MAX);
        const int padded = (tcount + CHW - 1) & ~(CHW - 1);
        for (int j = tid; j < padded; j += 128) {
            float4 e = (j < tcount) ? ge[base + j] : make_float4(1e9f, 0.f, 0.f, 0.f);
            e.x -= kbase;                       // window-relative arrival (1..WIN)
            sent[j] = e;
        }
        __syncthreads();

        float4 wc[CHW];
        #pragma unroll
        for (int q = 0; q < CHW; q++) wc[q] = wp[((int)sent[q].y) << 7];
        const int nch = padded / CHW;
        for (int c = 0; c < nch; c++) {
            float4 wn[CHW];
            if (c + 1 < nch) {
                #pragma unroll
                for (int q = 0; q < CHW; q++)
                    wn[q] = wp[((int)sent[(c + 1) * CHW + q].y) << 7];
            }
            #pragma unroll
            for (int q = 0; q < CHW; q++) {
                const float4 e = sent[c * CHW + q];
                while ((float)t_dt < e.x && t_dt <= WIN) {   // uniform across block
                    const float tf = (float)t_dt;
                    float4 cv;
                    cv.x = fmaf(tf, A0, -B0);
                    cv.y = fmaf(tf, A1, -B1);
                    cv.z = fmaf(tf, A2, -B2);
                    cv.w = fmaf(tf, A3, -B3);
                    schk[t_dt - 1][tid] = cv;                // STS, no scoreboard
                    t_dt++;
                }
                A0 = fmaf(wc[q].x, e.z, A0); B0 = fmaf(wc[q].x, e.w, B0);
                A1 = fmaf(wc[q].y, e.z, A1); B1 = fmaf(wc[q].y, e.w, B1);
                A2 = fmaf(wc[q].z, e.z, A2); B2 = fmaf(wc[q].z, e.w, B2);
                A3 = fmaf(wc[q].w, e.z, A3); B3 = fmaf(wc[q].w, e.w, B3);
            }
            #pragma unroll
            for (int q = 0; q < CHW; q++) wc[q] = wn[q];
        }
        __syncthreads();
    }
    while (t_dt <= WIN) {                                    // tail checkpoints
        const float tf = (float)t_dt;
        float4 cv;
        cv.x = fmaf(tf, A0, -B0);
        cv.y = fmaf(tf, A1, -B1);
        cv.z = fmaf(tf, A2, -B2);
        cv.w = fmaf(tf, A3, -B3);
        schk[t_dt - 1][tid] = cv;
        t_dt++;
    }

    // coalesced dump: 8 rows of 128 float4
    float* __restrict__ cp = g_C + ((b * NWE + W) * WIN) * OUT_SZ + o;
    #pragma unroll
    for (int dt = 0; dt < WIN; dt++)
        *(float4*)(cp + dt * OUT_SZ) = schk[dt][tid];

    float2* Pp = &g_P[(b * NWE + W) * OUT_SZ + o];
    *(float4*)(Pp)     = make_float4(A0, B0, A1, B1);
    *(float4*)(Pp + 2) = make_float4(A2, B2, A3, B3);
}

// ---------------------------------------------------------------------------
// Scan kernel: per (b,o) window recurrence A' = D(A+PA), B' = D(B+PB)-WIN*A'.
// Writes start state g_S for entry windows 0..NWE-1; directly evaluates the
// entry-free tail windows NWE..NW-1 (c1 = 0); first crossing -> atomicMin.
// ---------------------------------------------------------------------------
__global__ void __launch_bounds__(128) scan_kernel(float* __restrict__ out) {
    __shared__ float sthresh[WIN + 1];
    const int b = blockIdx.y;
    const int o = blockIdx.x * 128 + threadIdx.x;
    if (threadIdx.x >= 1 && threadIdx.x <= WIN) {
        const float dec = expf(1.0f - (float)threadIdx.x * (1.0f / TAU_F)) * (1.0f / TAU_F);
        sthresh[threadIdx.x] = V_TH / dec;
    }
    __syncthreads();

    float2 P[NWE];
    #pragma unroll
    for (int w = 0; w < NWE; w++) P[w] = g_P[(b * NWE + w) * OUT_SZ + o];

    float As = 0.f, Bs = 0.f;
    #pragma unroll
    for (int W = 0; W < NWE; W++) {
        if (W > 0) {
            As = DFACT * (As + P[W - 1].x);
            Bs = DFACT * (Bs + P[W - 1].y) - (float)WIN * As;
        }
        g_S[(b * NWE + W) * OUT_SZ + o] = make_float2(As, Bs);
    }
    int found = 0, result = 0;
    for (int W = NWE; W < NW && !found; W++) {
        const float pa = (W == NWE) ? P[NWE - 1].x : 0.f;
        const float pb = (W == NWE) ? P[NWE - 1].y : 0.f;
        As = DFACT * (As + pa);
        Bs = DFACT * (Bs + pb) - (float)WIN * As;
        int c = 1000;
        #pragma unroll
        for (int dt = 1; dt <= WIN; dt++) {
            if (fmaf((float)dt, As, -Bs) >= sthresh[dt]) c = min(c, dt);
        }
        if (c <= WIN) { found = 1; result = W * WIN + c; }
    }
    if (found)
        atomicMin((int*)out + b * OUT_SZ + o, __float_as_int((float)result));
}

// ---------------------------------------------------------------------------
// Test kernel: fully parallel threshold tests. Grid (NWE, B), 4 out/thread.
// Crossing at (W,dt) iff dt*As - Bs + c1[dt] >= th[dt]. Sparse atomicMin.
// ---------------------------------------------------------------------------
__global__ void __launch_bounds__(128) test_kernel(float* __restrict__ out) {
    __shared__ float sthresh[WIN + 1];
    const int W = blockIdx.x, b = blockIdx.y;
    const int tid = threadIdx.x;
    const int o = 4 * tid;

    if (tid >= 1 && tid <= WIN) {
        const float dec = expf(1.0f - (float)tid * (1.0f / TAU_F)) * (1.0f / TAU_F);
        sthresh[tid] = V_TH / dec;
    }
    __syncthreads();

    const float2* Sp = &g_S[(b * NWE + W) * OUT_SZ + o];
    const float4 s01 = *(const float4*)(Sp);
    const float4 s23 = *(const float4*)(Sp + 2);
    const float As0 = s01.x, Bs0 = s01.y, As1 = s01.z, Bs1 = s01.w;
    const float As2 = s23.x, Bs2 = s23.y, As3 = s23.z, Bs3 = s23.w;

    const float* __restrict__ cp = g_C + ((b * NWE + W) * WIN) * OUT_SZ + o;
    float4 cv[WIN];
    #pragma unroll
    for (int dt = 0; dt < WIN; dt++)
        cv[dt] = *(const float4*)(cp + dt * OUT_SZ);     // MLP = 8

    int cand0 = 1000, cand1 = 1000, cand2 = 1000, cand3 = 1000;
    #pragma unroll
    for (int dt = WIN; dt >= 1; dt--) {                  // descending -> plain assign
        const float tf = (float)dt;
        const float th = sthresh[dt];
        const float4 c = cv[dt - 1];
        if (fmaf(tf, As0, -Bs0) + c.x >= th) cand0 = dt;
        if (fmaf(tf, As1, -Bs1) + c.y >= th) cand1 = dt;
        if (fmaf(tf, As2, -Bs2) + c.z >= th) cand2 = dt;
        if (fmaf(tf, As3, -Bs3) + c.w >= th) cand3 = dt;
    }
    int* ob = (int*)out + b * OUT_SZ;
    const float Wbase = (float)(W * WIN);
    if (cand0 <= WIN) atomicMin(ob + o,     __float_as_int(Wbase + (float)cand0));
    if (cand1 <= WIN) atomicMin(ob + o + 1, __float_as_int(Wbase + (float)cand1));
    if (cand2 <= WIN) atomicMin(ob + o + 2, __float_as_int(Wbase + (float)cand2));
    if (cand3 <= WIN) atomicMin(ob + o + 3, __float_as_int(Wbase + (float)cand3));
}

// ---------------------------------------------------------------------------
extern "C" void kernel_launch(void* const* d_in, const int* in_sizes, int n_in,
                              void* d_out, int out_size) {
    const float* in_spike = (const float*)d_in[0];  // [B, IN]
    const float* weight   = (const float*)d_in[1];  // [OUT, IN]
    float* out = (float*)d_out;                     // [B, OUT]
    (void)in_sizes; (void)n_in; (void)out_size;

    prep_kernel<<<B_SZ + 128, 1024>>>(in_spike, weight, out);
    delta_kernel<<<dim3(NWE, B_SZ), 128>>>();
    scan_kernel<<<dim3(OUT_SZ / 128, B_SZ), 128>>>(out);
    test_kernel<<<dim3(NWE, B_SZ), 128>>>(out);
}

// round 12
// speedup vs baseline: 1.5976x; 1.0064x over previous
#include <cuda_runtime.h>
#include <math.h>

#define B_SZ   64
#define IN_SZ  1024
#define OUT_SZ 512
#define T_SZ   512
#define TAU_F  16.0f
#define V_TH   1.0f
#define WIN    8
#define NWE    32          // entry windows (spikes < 256 -> k <= 256)
#define NW     64          // total windows
#define ESTRIDE 1056
#define CHW    8           // prefetch depth in delta kernel
#define SENT_MAX 256
#define DFACT  0.60653065971263342f   // exp(-WIN/TAU) = exp(-0.5)
#define TH1    6.26569003f            // 16*exp(1/16 - 1)  (= V_TH/dec at dt=1)
#define THR    1.06449445891786f      // exp(1/16)

// Scratch (no dynamic allocation allowed)
__device__ float4 g_entries[B_SZ * ESTRIDE];        // {k, idx, u, p} sorted per batch
__device__ float  g_wT[IN_SZ * OUT_SZ];             // transposed weights [IN][OUT]
__device__ int    g_wstart[B_SZ * (NWE + 1)];       // per-batch window entry offsets
__device__ float2 g_P[B_SZ * NWE * OUT_SZ];         // per-window partials {PA, PB}
__device__ float2 g_S[B_SZ * NWE * OUT_SZ];         // per-window start state {A, B}
__device__ float  g_C[B_SZ * NWE * WIN * OUT_SZ];   // c1(dt) checkpoints (33.5 MB)

// ---------------------------------------------------------------------------
// Prep: blocks [0,64) bucket-sort spikes per batch (warp-shuffle scan) +
// window offsets + out init; blocks [64,192) float4 tiled transpose.
// ---------------------------------------------------------------------------
__global__ void __launch_bounds__(1024) prep_kernel(const float* __restrict__ in_spike,
                                                    const float* __restrict__ w,
                                                    float* __restrict__ out) {
    __shared__ int   hist[512];
    __shared__ int   scanv[512];
    __shared__ int   offs[512];
    __shared__ int   wsum[16];
    __shared__ float tile[64][65];

    const int bid = blockIdx.x;
    const int i   = threadIdx.x;

    if (bid < B_SZ) {
        const int b = bid;
        if (i < 512) { hist[i] = 0; out[b * OUT_SZ + i] = 512.0f; }  // init for atomicMin
        __syncthreads();

        const float s = in_spike[b * IN_SZ + i];
        int k = (int)floorf(s) + 1;
        k = max(1, min(k, NWE * WIN));           // k in [1, 256]
        atomicAdd(&hist[k], 1);
        __syncthreads();

        int h0 = 0, incl = 0;
        if (i < 512) {
            h0 = hist[i]; incl = h0;
            #pragma unroll
            for (int d = 1; d < 32; d <<= 1) {
                int n = __shfl_up_sync(0xffffffffu, incl, d);
                if ((i & 31) >= d) incl += n;
            }
            if ((i & 31) == 31) wsum[i >> 5] = incl;
        }
        __syncthreads();
        if (i < 16) {
            int s2 = wsum[i];
            #pragma unroll
            for (int d = 1; d < 16; d <<= 1) {
                int n = __shfl_up_sync(0x0000ffffu, s2, d);
                if (i >= d) s2 += n;
            }
            wsum[i] = s2;
        }
        __syncthreads();
        if (i < 512) {
            const int wrp = i >> 5;
            if (wrp > 0) incl += wsum[wrp - 1];
            scanv[i] = incl;          // inclusive
            offs[i]  = incl - h0;     // exclusive
        }
        __syncthreads();
        if (i <= NWE) g_wstart[b * (NWE + 1) + i] = (i == 0) ? 0 : scanv[i * WIN];

        const int pos = atomicAdd(&offs[k], 1);
        const int t0k = (k - 1) & ~(WIN - 1);
        const float rel = s - (float)t0k;              // [0, WIN)
        const float u = expf(rel * (1.0f / TAU_F));
        const float p = rel * u;
        g_entries[b * ESTRIDE + pos] = make_float4((float)k, (float)i, u, p);
    } else {
        // transpose 64x64 tile: w[OUT][IN] -> g_wT[IN][OUT]
        const int tb = bid - B_SZ;                 // 0..127
        const int i0 = (tb & 15) * 64;             // IN tile
        const int o0 = (tb >> 4) * 64;             // OUT tile
        const int tx = i & 15, ty = i >> 4;        // 16 x 64
        const float4 v = *(const float4*)&w[(o0 + ty) * IN_SZ + i0 + 4 * tx];
        tile[4 * tx + 0][ty] = v.x;
        tile[4 * tx + 1][ty] = v.y;
        tile[4 * tx + 2][ty] = v.z;
        tile[4 * tx + 3][ty] = v.w;
        __syncthreads();
        float4 r;
        r.x = tile[ty][4 * tx + 0];
        r.y = tile[ty][4 * tx + 1];
        r.z = tile[ty][4 * tx + 2];
        r.w = tile[ty][4 * tx + 3];
        *(float4*)&g_wT[(i0 + ty) * OUT_SZ + o0 + 4 * tx] = r;
    }
}

// ---------------------------------------------------------------------------
// Delta kernel (single entry x weight gather pass). Per (b, W, o):
// checkpoints c1(dt) = dt*dA(dt) - dB(dt) (SMEM staged, coalesced dump) and
// window partials (PA,PB). 4 outputs/thread, grid (NWE, B), CHW=8 prefetch.
// ---------------------------------------------------------------------------
__global__ void __launch_bounds__(128) delta_kernel() {
    __shared__ float4 sent[SENT_MAX];          // 4 KB
    __shared__ float4 schk[WIN][128];          // 16 KB checkpoint staging
    const int W = blockIdx.x, b = blockIdx.y;
    const int tid = threadIdx.x;
    const int o = 4 * tid;

    const int start = g_wstart[b * (NWE + 1) + W];
    const int count = g_wstart[b * (NWE + 1) + W + 1] - start;
    const float kbase = (float)(W * WIN);

    float A0 = 0.f, B0 = 0.f, A1 = 0.f, B1 = 0.f;
    float A2 = 0.f, B2 = 0.f, A3 = 0.f, B3 = 0.f;

    const float4* __restrict__ ge = g_entries + b * ESTRIDE + start;
    const float4* __restrict__ wp = (const float4*)g_wT + tid;

    int t_dt = 1;
    for (int base = 0; base < count; base += SENT_MAX) {
        const int tcount = min(count - base, SENT_MAX);
        const int padded = (tcount + CHW - 1) & ~(CHW - 1);
        for (int j = tid; j < padded; j += 128) {
            float4 e = (j < tcount) ? ge[base + j] : make_float4(1e9f, 0.f, 0.f, 0.f);
            e.x -= kbase;                       // window-relative arrival (1..WIN)
            sent[j] = e;
        }
        __syncthreads();

        float4 wc[CHW];
        #pragma unroll
        for (int q = 0; q < CHW; q++) wc[q] = wp[((int)sent[q].y) << 7];
        const int nch = padded / CHW;
        for (int c = 0; c < nch; c++) {
            float4 wn[CHW];
            if (c + 1 < nch) {
                #pragma unroll
                for (int q = 0; q < CHW; q++)
                    wn[q] = wp[((int)sent[(c + 1) * CHW + q].y) << 7];
            }
            #pragma unroll
            for (int q = 0; q < CHW; q++) {
                const float4 e = sent[c * CHW + q];
                while ((float)t_dt < e.x && t_dt <= WIN) {   // uniform across block
                    const float tf = (float)t_dt;
                    float4 cv;
                    cv.x = fmaf(tf, A0, -B0);
                    cv.y = fmaf(tf, A1, -B1);
                    cv.z = fmaf(tf, A2, -B2);
                    cv.w = fmaf(tf, A3, -B3);
                    schk[t_dt - 1][tid] = cv;                // STS, no scoreboard
                    t_dt++;
                }
                A0 = fmaf(wc[q].x, e.z, A0); B0 = fmaf(wc[q].x, e.w, B0);
                A1 = fmaf(wc[q].y, e.z, A1); B1 = fmaf(wc[q].y, e.w, B1);
                A2 = fmaf(wc[q].z, e.z, A2); B2 = fmaf(wc[q].z, e.w, B2);
                A3 = fmaf(wc[q].w, e.z, A3); B3 = fmaf(wc[q].w, e.w, B3);
            }
            #pragma unroll
            for (int q = 0; q < CHW; q++) wc[q] = wn[q];
        }
        __syncthreads();
    }
    while (t_dt <= WIN) {                                    // tail checkpoints
        const float tf = (float)t_dt;
        float4 cv;
        cv.x = fmaf(tf, A0, -B0);
        cv.y = fmaf(tf, A1, -B1);
        cv.z = fmaf(tf, A2, -B2);
        cv.w = fmaf(tf, A3, -B3);
        schk[t_dt - 1][tid] = cv;
        t_dt++;
    }

    // coalesced dump: 8 rows of 128 float4
    float* __restrict__ cp = g_C + ((b * NWE + W) * WIN) * OUT_SZ + o;
    #pragma unroll
    for (int dt = 0; dt < WIN; dt++)
        *(float4*)(cp + dt * OUT_SZ) = schk[dt][tid];

    float2* Pp = &g_P[(b * NWE + W) * OUT_SZ + o];
    *(float4*)(Pp)     = make_float4(A0, B0, A1, B1);
    *(float4*)(Pp + 2) = make_float4(A2, B2, A3, B3);
}

// ---------------------------------------------------------------------------
// Scan kernel: per (b,o) window recurrence A' = D(A+PA), B' = D(B+PB)-WIN*A'.
// Writes start state g_S for entry windows; evaluates entry-free tail
// windows (c1 = 0) with register threshold table; atomicMin.
// ---------------------------------------------------------------------------
__global__ void __launch_bounds__(128) scan_kernel(float* __restrict__ out) {
    const int b = blockIdx.y;
    const int o = blockIdx.x * 128 + threadIdx.x;

    float th[WIN];
    th[0] = TH1;
    #pragma unroll
    for (int j = 1; j < WIN; j++) th[j] = th[j - 1] * THR;

    float2 P[NWE];
    #pragma unroll
    for (int w = 0; w < NWE; w++) P[w] = g_P[(b * NWE + w) * OUT_SZ + o];

    float As = 0.f, Bs = 0.f;
    #pragma unroll
    for (int W = 0; W < NWE; W++) {
        if (W > 0) {
            As = DFACT * (As + P[W - 1].x);
            Bs = DFACT * (Bs + P[W - 1].y) - (float)WIN * As;
        }
        g_S[(b * NWE + W) * OUT_SZ + o] = make_float2(As, Bs);
    }
    int found = 0, result = 0;
    for (int W = NWE; W < NW && !found; W++) {
        const float pa = (W == NWE) ? P[NWE - 1].x : 0.f;
        const float pb = (W == NWE) ? P[NWE - 1].y : 0.f;
        As = DFACT * (As + pa);
        Bs = DFACT * (Bs + pb) - (float)WIN * As;
        int c = 1000;
        #pragma unroll
        for (int dt = WIN; dt >= 1; dt--) {
            if (fmaf((float)dt, As, -Bs) >= th[dt - 1]) c = dt;
        }
        if (c <= WIN) { found = 1; result = W * WIN + c; }
    }
    if (found)
        atomicMin((int*)out + b * OUT_SZ + o, __float_as_int((float)result));
}

// ---------------------------------------------------------------------------
// Test kernel: 2 windows per block, grid (NWE/2, B), 4 out/thread.
// All 20 loads issued up-front (MLP ~20), register threshold table,
// descending-dt tests (W+1 then W so earlier times overwrite), one
// atomicMin per output.
// ---------------------------------------------------------------------------
__global__ void __launch_bounds__(128) test_kernel(float* __restrict__ out) {
    const int W0 = blockIdx.x * 2, b = blockIdx.y;
    const int tid = threadIdx.x;
    const int o = 4 * tid;

    // start states for both windows
    const float2* Sp0 = &g_S[(b * NWE + W0) * OUT_SZ + o];
    const float2* Sp1 = &g_S[(b * NWE + W0 + 1) * OUT_SZ + o];
    const float4 sA0 = *(const float4*)(Sp0);
    const float4 sB0 = *(const float4*)(Sp0 + 2);
    const float4 sA1 = *(const float4*)(Sp1);
    const float4 sB1 = *(const float4*)(Sp1 + 2);

    // checkpoint rows for both windows
    const float* __restrict__ cp0 = g_C + ((b * NWE + W0) * WIN) * OUT_SZ + o;
    const float* __restrict__ cp1 = cp0 + WIN * OUT_SZ;
    float4 cv0[WIN], cv1[WIN];
    #pragma unroll
    for (int dt = 0; dt < WIN; dt++) cv0[dt] = *(const float4*)(cp0 + dt * OUT_SZ);
    #pragma unroll
    for (int dt = 0; dt < WIN; dt++) cv1[dt] = *(const float4*)(cp1 + dt * OUT_SZ);

    float th[WIN];
    th[0] = TH1;
    #pragma unroll
    for (int j = 1; j < WIN; j++) th[j] = th[j - 1] * THR;

    int cand0 = 100000, cand1 = 100000, cand2 = 100000, cand3 = 100000;

    // window W0+1 first (later times), descending dt
    #pragma unroll
    for (int dt = WIN; dt >= 1; dt--) {
        const float tf = (float)dt;
        const float t1 = th[dt - 1];
        const float4 c = cv1[dt - 1];
        const int tt = (W0 + 1) * WIN + dt;
        if (fmaf(tf, sA1.x, -sA1.y) + c.x >= t1) cand0 = tt;
        if (fmaf(tf, sA1.z, -sA1.w) + c.y >= t1) cand1 = tt;
        if (fmaf(tf, sB1.x, -sB1.y) + c.z >= t1) cand2 = tt;
        if (fmaf(tf, sB1.z, -sB1.w) + c.w >= t1) cand3 = tt;
    }
    // window W0 second (earlier times overwrite), descending dt
    #pragma unroll
    for (int dt = WIN; dt >= 1; dt--) {
        const float tf = (float)dt;
        const float t1 = th[dt - 1];
        const float4 c = cv0[dt - 1];
        const int tt = W0 * WIN + dt;
        if (fmaf(tf, sA0.x, -sA0.y) + c.x >= t1) cand0 = tt;
        if (fmaf(tf, sA0.z, -sA0.w) + c.y >= t1) cand1 = tt;
        if (fmaf(tf, sB0.x, -sB0.y) + c.z >= t1) cand2 = tt;
        if (fmaf(tf, sB0.z, -sB0.w) + c.w >= t1) cand3 = tt;
    }

    int* ob = (int*)out + b * OUT_SZ;
    if (cand0 < 100000) atomicMin(ob + o,     __float_as_int((float)cand0));
    if (cand1 < 100000) atomicMin(ob + o + 1, __float_as_int((float)cand1));
    if (cand2 < 100000) atomicMin(ob + o + 2, __float_as_int((float)cand2));
    if (cand3 < 100000) atomicMin(ob + o + 3, __float_as_int((float)cand3));
}

// ---------------------------------------------------------------------------
extern "C" void kernel_launch(void* const* d_in, const int* in_sizes, int n_in,
                              void* d_out, int out_size) {
    const float* in_spike = (const float*)d_in[0];  // [B, IN]
    const float* weight   = (const float*)d_in[1];  // [OUT, IN]
    float* out = (float*)d_out;                     // [B, OUT]
    (void)in_sizes; (void)n_in; (void)out_size;

    prep_kernel<<<B_SZ + 128, 1024>>>(in_spike, weight, out);
    delta_kernel<<<dim3(NWE, B_SZ), 128>>>();
    scan_kernel<<<dim3(OUT_SZ / 128, B_SZ), 128>>>(out);
    test_kernel<<<dim3(NWE / 2, B_SZ), 128>>>(out);
}